// round 7
// baseline (speedup 1.0000x reference)
#include <cuda_runtime.h>
#include <cstdint>

#define NUSER 50000
#define NITEM 100000
#define NN    150000
#define DD    64
#define EE    2400000

// scratch: static device globals (no runtime allocation allowed)
__device__ float g_ego[NN * DD];   // 38.4 MB
__device__ float g_side[NN * DD];  // 38.4 MB

// tiny shim so ncu (-s 5 -c 1) lands on a layer_kernel launch
__global__ void prof_shim_kernel() {}

// ---------------------------------------------------------------------------
// init: ego = concat(user_emb, item_emb); side = 0; out[:, 0:64] = ego (raw)
// ---------------------------------------------------------------------------
__global__ void init_kernel(const float* __restrict__ ue,
                            const float* __restrict__ ie,
                            float* __restrict__ out) {
    int i4 = blockIdx.x * blockDim.x + threadIdx.x;  // float4 index
    if (i4 >= NN * 16) return;
    int row = i4 >> 4;
    int q   = i4 & 15;
    float4 v;
    if (row < NUSER) v = reinterpret_cast<const float4*>(ue)[i4];
    else             v = reinterpret_cast<const float4*>(ie)[i4 - NUSER * 16];
    reinterpret_cast<float4*>(g_ego)[i4]  = v;
    reinterpret_cast<float4*>(g_side)[i4] = make_float4(0.f, 0.f, 0.f, 0.f);
    reinterpret_cast<float4*>(out)[row * 64 + q] = v;
}

// ---------------------------------------------------------------------------
// SpMM: side[r] += vals[e] * ego[c].  4 threads/edge, each owns 4 float4s
// (MLP=4: all 4 gathers issued before the 4 REDs).
// ---------------------------------------------------------------------------
__global__ void spmm_kernel(const float* __restrict__ vals,
                            const int*   __restrict__ rows,
                            const int*   __restrict__ cols) {
    int t = blockIdx.x * blockDim.x + threadIdx.x;  // EE*4 = 9.6M
    if (t >= EE * 4) return;
    int e = t >> 2;
    int q = t & 3;
    int c   = __ldg(cols + e);
    int r   = __ldg(rows + e);
    float v = __ldg(vals + e);
    const float4* src = reinterpret_cast<const float4*>(g_ego + (size_t)c * DD) + q;
    float4*       dst = reinterpret_cast<float4*>(g_side + (size_t)r * DD) + q;

    float4 x[4];
#pragma unroll
    for (int j = 0; j < 4; j++) x[j] = __ldg(src + j * 4);   // independent: MLP=4
#pragma unroll
    for (int j = 0; j < 4; j++) {
        x[j].x *= v; x[j].y *= v; x[j].z *= v; x[j].w *= v;
#if __CUDA_ARCH__ >= 900
        atomicAdd(dst + j * 4, x[j]);
#else
        float* p = reinterpret_cast<float*>(dst + j * 4);
        atomicAdd(p + 0, x[j].x); atomicAdd(p + 1, x[j].y);
        atomicAdd(p + 2, x[j].z); atomicAdd(p + 3, x[j].w);
#endif
    }
}

// ---------------------------------------------------------------------------
// tf32 helpers
// ---------------------------------------------------------------------------
__device__ __forceinline__ uint32_t f2tf32(float f) {
    uint32_t u;
    asm("cvt.rna.tf32.f32 %0, %1;" : "=r"(u) : "f"(f));
    return u;
}
__device__ __forceinline__ void split_tf32(float f, uint32_t& hi, uint32_t& lo) {
    hi = f2tf32(f);
    lo = f2tf32(f - __uint_as_float(hi));
}
__device__ __forceinline__ void mma_tf32(float c[4],
                                         uint32_t a0, uint32_t a1, uint32_t a2, uint32_t a3,
                                         uint32_t b0, uint32_t b1) {
    asm volatile(
        "mma.sync.aligned.m16n8k8.row.col.f32.tf32.tf32.f32 "
        "{%0,%1,%2,%3}, {%4,%5,%6,%7}, {%8,%9}, {%0,%1,%2,%3};"
        : "+f"(c[0]), "+f"(c[1]), "+f"(c[2]), "+f"(c[3])
        : "r"(a0), "r"(a1), "r"(a2), "r"(a3), "r"(b0), "r"(b1));
}

// ---------------------------------------------------------------------------
// Fused dense layer on tensor cores (3xTF32, mma.sync m16n8k8):
//   Block = 256 thr / 8 warps, tile 128 rows x 64 cols.
//   Warp w owns rows [w*16, w*16+16) x all 64 cols, BOTH GEMMs.
//   sum = leaky(side@Wg+bg); bi = leaky((ego*side)@Wb+bb); ego = sum+bi
//   out[:, koff:+64] = l2norm(ego); side cleared during staging.
// Dynamic smem, padded row stride 68 floats (17 float4): A-frag LDS
// conflict-free, W-frag 2-way.
// ---------------------------------------------------------------------------
#define SPAD   68           // floats per padded row
#define SPAD4  17           // float4 per padded row
// float4 offsets in dynamic smem
#define OFF4_WG 0                       // 64*17  = 1088
#define OFF4_WB 1088
#define OFF4_S  2176                    // 128*17 = 2176
#define OFF4_ES 4352
#define OFF4_BG 6528
#define OFF4_BB 6544
#define SMEM_BYTES ((6560) * 16)        // 104960 B

__global__ __launch_bounds__(256) void layer_kernel(
    const float* __restrict__ Wg, const float* __restrict__ bg,
    const float* __restrict__ Wb, const float* __restrict__ bb,
    float* __restrict__ out, int koff) {
    extern __shared__ float sm[];
    float4* sm4 = reinterpret_cast<float4*>(sm);

    int tid = threadIdx.x;
    int rowbase = blockIdx.x * 128;

    // ---- stage weights: 1024 float4 each ----
#pragma unroll
    for (int i = 0; i < 4; i++) {
        int id = tid + i * 256;
        int k  = id >> 4, lc = id & 15;
        sm4[OFF4_WG + k * SPAD4 + lc] = reinterpret_cast<const float4*>(Wg)[id];
        sm4[OFF4_WB + k * SPAD4 + lc] = reinterpret_cast<const float4*>(Wb)[id];
    }
    // ---- stage S / ES: 2048 float4 each; clear side ----
#pragma unroll
    for (int i = 0; i < 8; i++) {
        int id = tid + i * 256;
        int lr = id >> 4, lc = id & 15;
        int grow = rowbase + lr;
        float4 sv = make_float4(0.f, 0.f, 0.f, 0.f);
        float4 ev = sv;
        if (grow < NN) {
            int gi4 = grow * 16 + lc;
            sv = reinterpret_cast<float4*>(g_side)[gi4];
            ev = reinterpret_cast<float4*>(g_ego)[gi4];
            reinterpret_cast<float4*>(g_side)[gi4] = make_float4(0.f, 0.f, 0.f, 0.f);
        }
        sm4[OFF4_S  + lr * SPAD4 + lc] = sv;
        sm4[OFF4_ES + lr * SPAD4 + lc] =
            make_float4(ev.x * sv.x, ev.y * sv.y, ev.z * sv.z, ev.w * sv.w);
    }
    // ---- stage biases ----
    if (tid < 16)              sm4[OFF4_BG + tid]      = reinterpret_cast<const float4*>(bg)[tid];
    else if (tid < 32)         sm4[OFF4_BB + tid - 16] = reinterpret_cast<const float4*>(bb)[tid - 16];
    __syncthreads();

    const float* sS  = sm + OFF4_S  * 4;
    const float* sES = sm + OFF4_ES * 4;
    const float* sWg_ = sm + OFF4_WG * 4;
    const float* sWb_ = sm + OFF4_WB * 4;
    const float* sBg = sm + OFF4_BG * 4;
    const float* sBb = sm + OFF4_BB * 4;

    int warp = tid >> 5;
    int lane = tid & 31;
    int lr = lane >> 2;      // 0..7  (fragment row group)
    int lc = lane & 3;       // 0..3  (fragment col group)
    int r0 = warp * 16;      // block-local row base for this warp

    float cg[8][4], cb[8][4];
#pragma unroll
    for (int nt = 0; nt < 8; nt++)
#pragma unroll
        for (int i = 0; i < 4; i++) { cg[nt][i] = 0.f; cb[nt][i] = 0.f; }

#pragma unroll
    for (int k = 0; k < 8; k++) {
        int k8 = k * 8;
        // A fragments (S and ES), split hi/lo
        int abase = (r0 + lr) * SPAD + k8 + lc;
        float fs0 = sS [abase];               float fs1 = sS [abase + 8 * SPAD];
        float fs2 = sS [abase + 4];           float fs3 = sS [abase + 8 * SPAD + 4];
        float fe0 = sES[abase];               float fe1 = sES[abase + 8 * SPAD];
        float fe2 = sES[abase + 4];           float fe3 = sES[abase + 8 * SPAD + 4];
        uint32_t sh[4], sl[4], eh[4], el[4];
        split_tf32(fs0, sh[0], sl[0]); split_tf32(fs1, sh[1], sl[1]);
        split_tf32(fs2, sh[2], sl[2]); split_tf32(fs3, sh[3], sl[3]);
        split_tf32(fe0, eh[0], el[0]); split_tf32(fe1, eh[1], el[1]);
        split_tf32(fe2, eh[2], el[2]); split_tf32(fe3, el[3] = 0, el[3]);  // placeholder fix below
        // (redo fe3 split properly)
        split_tf32(fe3, eh[3], el[3]);

#pragma unroll
        for (int nt = 0; nt < 8; nt++) {
            int bbase = (k8 + lc) * SPAD + nt * 8 + lr;
            // ---- GEMM 1: S @ Wg ----
            {
                float w0 = sWg_[bbase];
                float w1 = sWg_[bbase + 4 * SPAD];
                uint32_t wh0, wl0, wh1, wl1;
                split_tf32(w0, wh0, wl0);
                split_tf32(w1, wh1, wl1);
                mma_tf32(cg[nt], sl[0], sl[1], sl[2], sl[3], wh0, wh1);
                mma_tf32(cg[nt], sh[0], sh[1], sh[2], sh[3], wl0, wl1);
                mma_tf32(cg[nt], sh[0], sh[1], sh[2], sh[3], wh0, wh1);
            }
            // ---- GEMM 2: ES @ Wb ----
            {
                float w0 = sWb_[bbase];
                float w1 = sWb_[bbase + 4 * SPAD];
                uint32_t wh0, wl0, wh1, wl1;
                split_tf32(w0, wh0, wl0);
                split_tf32(w1, wh1, wl1);
                mma_tf32(cb[nt], el[0], el[1], el[2], el[3], wh0, wh1);
                mma_tf32(cb[nt], eh[0], eh[1], eh[2], eh[3], wl0, wl1);
                mma_tf32(cb[nt], eh[0], eh[1], eh[2], eh[3], wh0, wh1);
            }
        }
    }

    // ---- epilogue: bias + leaky + combine + l2norm + stores ----
    float2 neA[8], neB[8];     // rows (r0+lr) and (r0+lr+8)
    float sA = 0.f, sB = 0.f;
#pragma unroll
    for (int nt = 0; nt < 8; nt++) {
        int col0 = nt * 8 + 2 * lc;
        float bg0 = sBg[col0], bg1 = sBg[col0 + 1];
        float bb0 = sBb[col0], bb1 = sBb[col0 + 1];
        float g0 = cg[nt][0] + bg0;  g0 = (g0 > 0.f) ? g0 : 0.2f * g0;
        float g1 = cg[nt][1] + bg1;  g1 = (g1 > 0.f) ? g1 : 0.2f * g1;
        float g2 = cg[nt][2] + bg0;  g2 = (g2 > 0.f) ? g2 : 0.2f * g2;
        float g3 = cg[nt][3] + bg1;  g3 = (g3 > 0.f) ? g3 : 0.2f * g3;
        float h0 = cb[nt][0] + bb0;  h0 = (h0 > 0.f) ? h0 : 0.2f * h0;
        float h1 = cb[nt][1] + bb1;  h1 = (h1 > 0.f) ? h1 : 0.2f * h1;
        float h2 = cb[nt][2] + bb0;  h2 = (h2 > 0.f) ? h2 : 0.2f * h2;
        float h3 = cb[nt][3] + bb1;  h3 = (h3 > 0.f) ? h3 : 0.2f * h3;
        float a0 = g0 + h0, a1 = g1 + h1;
        float b0 = g2 + h2, b1 = g3 + h3;
        neA[nt] = make_float2(a0, a1);
        neB[nt] = make_float2(b0, b1);
        sA = fmaf(a0, a0, fmaf(a1, a1, sA));
        sB = fmaf(b0, b0, fmaf(b1, b1, sB));
    }
    // reduce sum of squares across the 4 lanes sharing a row (lc bits)
    sA += __shfl_xor_sync(0xffffffffu, sA, 1);
    sA += __shfl_xor_sync(0xffffffffu, sA, 2);
    sB += __shfl_xor_sync(0xffffffffu, sB, 1);
    sB += __shfl_xor_sync(0xffffffffu, sB, 2);
    float invA = 1.f / fmaxf(sqrtf(sA), 1e-12f);
    float invB = 1.f / fmaxf(sqrtf(sB), 1e-12f);

    int growA = rowbase + r0 + lr;
    int growB = growA + 8;
#pragma unroll
    for (int nt = 0; nt < 8; nt++) {
        int col0 = nt * 8 + 2 * lc;
        if (growA < NN) {
            *reinterpret_cast<float2*>(&g_ego[growA * 64 + col0]) = neA[nt];
            *reinterpret_cast<float2*>(&out[growA * 256 + koff + col0]) =
                make_float2(neA[nt].x * invA, neA[nt].y * invA);
        }
        if (growB < NN) {
            *reinterpret_cast<float2*>(&g_ego[growB * 64 + col0]) = neB[nt];
            *reinterpret_cast<float2*>(&out[growB * 256 + koff + col0]) =
                make_float2(neB[nt].x * invB, neB[nt].y * invB);
        }
    }
}

// ---------------------------------------------------------------------------
extern "C" void kernel_launch(void* const* d_in, const int* in_sizes, int n_in,
                              void* d_out, int out_size) {
    const float* ue = (const float*)d_in[0];
    const float* ie = (const float*)d_in[1];
    const float* Wg[3] = {(const float*)d_in[2],  (const float*)d_in[6],  (const float*)d_in[10]};
    const float* bg[3] = {(const float*)d_in[3],  (const float*)d_in[7],  (const float*)d_in[11]};
    const float* Wb[3] = {(const float*)d_in[4],  (const float*)d_in[8],  (const float*)d_in[12]};
    const float* bb[3] = {(const float*)d_in[5],  (const float*)d_in[9],  (const float*)d_in[13]};
    const float* vals = (const float*)d_in[14];
    const int*   rows = (const int*)d_in[15];
    const int*   cols = (const int*)d_in[16];
    float* out = (float*)d_out;

    cudaFuncSetAttribute(layer_kernel,
                         cudaFuncAttributeMaxDynamicSharedMemorySize, SMEM_BYTES);

    prof_shim_kernel<<<1, 1>>>();   // shifts ncu -s 5 onto a layer_kernel launch
    init_kernel<<<(NN * 16 + 255) / 256, 256>>>(ue, ie, out);
    for (int k = 0; k < 3; k++) {
        spmm_kernel<<<(EE * 4 + 255) / 256, 256>>>(vals, rows, cols);
        layer_kernel<<<(NN + 127) / 128, 256, SMEM_BYTES>>>(
            Wg[k], bg[k], Wb[k], bb[k], out, (k + 1) * 64);
    }
}

// round 8
// speedup vs baseline: 1.0869x; 1.0869x over previous
#include <cuda_runtime.h>
#include <cstdint>

#define NUSER 50000
#define NITEM 100000
#define NN    150000
#define DD    64
#define EE    2400000

// scratch: static device globals (no runtime allocation allowed)
__device__ float g_ego[NN * DD];   // 38.4 MB
__device__ float g_side[NN * DD];  // 38.4 MB

// tiny shim so ncu (-s 5 -c 1) lands on a layer_kernel launch
__global__ void prof_shim_kernel() {}

// ---------------------------------------------------------------------------
// init: ego = concat(user_emb, item_emb); side = 0; out[:, 0:64] = ego (raw)
// ---------------------------------------------------------------------------
__global__ void init_kernel(const float* __restrict__ ue,
                            const float* __restrict__ ie,
                            float* __restrict__ out) {
    int i4 = blockIdx.x * blockDim.x + threadIdx.x;  // float4 index
    if (i4 >= NN * 16) return;
    int row = i4 >> 4;
    int q   = i4 & 15;
    float4 v;
    if (row < NUSER) v = reinterpret_cast<const float4*>(ue)[i4];
    else             v = reinterpret_cast<const float4*>(ie)[i4 - NUSER * 16];
    reinterpret_cast<float4*>(g_ego)[i4]  = v;
    reinterpret_cast<float4*>(g_side)[i4] = make_float4(0.f, 0.f, 0.f, 0.f);
    reinterpret_cast<float4*>(out)[row * 64 + q] = v;
}

// ---------------------------------------------------------------------------
// SpMM: side[r] += vals[e] * ego[c].  4 threads/edge, each owns 4 float4s
// (MLP=4: all 4 gathers issued before the 4 REDs).
// ---------------------------------------------------------------------------
__global__ void spmm_kernel(const float* __restrict__ vals,
                            const int*   __restrict__ rows,
                            const int*   __restrict__ cols) {
    int t = blockIdx.x * blockDim.x + threadIdx.x;  // EE*4 = 9.6M
    if (t >= EE * 4) return;
    int e = t >> 2;
    int q = t & 3;
    int c   = __ldg(cols + e);
    int r   = __ldg(rows + e);
    float v = __ldg(vals + e);
    const float4* src = reinterpret_cast<const float4*>(g_ego + (size_t)c * DD) + q;
    float4*       dst = reinterpret_cast<float4*>(g_side + (size_t)r * DD) + q;

    float4 x[4];
#pragma unroll
    for (int j = 0; j < 4; j++) x[j] = __ldg(src + j * 4);   // independent: MLP=4
#pragma unroll
    for (int j = 0; j < 4; j++) {
        x[j].x *= v; x[j].y *= v; x[j].z *= v; x[j].w *= v;
#if __CUDA_ARCH__ >= 900
        atomicAdd(dst + j * 4, x[j]);
#else
        float* p = reinterpret_cast<float*>(dst + j * 4);
        atomicAdd(p + 0, x[j].x); atomicAdd(p + 1, x[j].y);
        atomicAdd(p + 2, x[j].z); atomicAdd(p + 3, x[j].w);
#endif
    }
}

// ---------------------------------------------------------------------------
// tf32 helpers
// ---------------------------------------------------------------------------
__device__ __forceinline__ uint32_t f2tf32(float f) {
    uint32_t u;
    asm("cvt.rna.tf32.f32 %0, %1;" : "=r"(u) : "f"(f));
    return u;
}
__device__ __forceinline__ void split2(float f, float& hi, float& lo) {
    uint32_t h = f2tf32(f);
    hi = __uint_as_float(h);
    lo = __uint_as_float(f2tf32(f - hi));
}
__device__ __forceinline__ void mma_tf32(float c[4],
                                         uint32_t a0, uint32_t a1, uint32_t a2, uint32_t a3,
                                         uint32_t b0, uint32_t b1) {
    asm volatile(
        "mma.sync.aligned.m16n8k8.row.col.f32.tf32.tf32.f32 "
        "{%0,%1,%2,%3}, {%4,%5,%6,%7}, {%8,%9}, {%0,%1,%2,%3};"
        : "+f"(c[0]), "+f"(c[1]), "+f"(c[2]), "+f"(c[3])
        : "r"(a0), "r"(a1), "r"(a2), "r"(a3), "r"(b0), "r"(b1));
}

// ---------------------------------------------------------------------------
// Fused dense layer on tensor cores (3xTF32, mma.sync m16n8k8), with ALL
// hi/lo splits precomputed into smem at staging. Inner loop = LDS + HMMA only.
//   Block = 256 thr / 8 warps, tile 128 rows x 64 cols.
//   Warp w owns rows [w*16, w*16+16) x all 64 cols, BOTH GEMMs.
// smem 208KB (1 block/SM): W stride 72 floats (conflict-free B frags),
// A stride 68 floats (conflict-free A frags).
// ---------------------------------------------------------------------------
#define WPAD   72
#define WPAD4  18
#define APAD   68
#define APAD4  17
// float4 offsets
#define OFF4_WGH 0                        // 64*18 = 1152 each
#define OFF4_WGL 1152
#define OFF4_WBH 2304
#define OFF4_WBL 3456
#define OFF4_SH  4608                     // 128*17 = 2176 each
#define OFF4_SL  6784
#define OFF4_ESH 8960
#define OFF4_ESL 11136
#define SMEM_BYTES (13312 * 16)           // 212992 B

__global__ __launch_bounds__(256) void layer_kernel(
    const float* __restrict__ Wg, const float* __restrict__ bg,
    const float* __restrict__ Wb, const float* __restrict__ bb,
    float* __restrict__ out, int koff) {
    extern __shared__ float sm[];
    float4* sm4 = reinterpret_cast<float4*>(sm);

    int tid = threadIdx.x;
    int rowbase = blockIdx.x * 128;

    // ---- stage weights, pre-split hi/lo ----
#pragma unroll
    for (int i = 0; i < 4; i++) {
        int id = tid + i * 256;           // float4 id, 0..1023
        int k  = id >> 4, lc = id & 15;
        float4 wg4 = reinterpret_cast<const float4*>(Wg)[id];
        float4 wb4 = reinterpret_cast<const float4*>(Wb)[id];
        float4 h, l;
        split2(wg4.x, h.x, l.x); split2(wg4.y, h.y, l.y);
        split2(wg4.z, h.z, l.z); split2(wg4.w, h.w, l.w);
        sm4[OFF4_WGH + k * WPAD4 + lc] = h;
        sm4[OFF4_WGL + k * WPAD4 + lc] = l;
        split2(wb4.x, h.x, l.x); split2(wb4.y, h.y, l.y);
        split2(wb4.z, h.z, l.z); split2(wb4.w, h.w, l.w);
        sm4[OFF4_WBH + k * WPAD4 + lc] = h;
        sm4[OFF4_WBL + k * WPAD4 + lc] = l;
    }
    // ---- stage S / ES pre-split; clear side ----
#pragma unroll
    for (int i = 0; i < 8; i++) {
        int id = tid + i * 256;           // float4 id, 0..2047
        int lr = id >> 4, lc = id & 15;
        int grow = rowbase + lr;
        float4 sv = make_float4(0.f, 0.f, 0.f, 0.f);
        float4 ev = sv;
        if (grow < NN) {
            int gi4 = grow * 16 + lc;
            sv = reinterpret_cast<float4*>(g_side)[gi4];
            ev = reinterpret_cast<float4*>(g_ego)[gi4];
            reinterpret_cast<float4*>(g_side)[gi4] = make_float4(0.f, 0.f, 0.f, 0.f);
        }
        float4 es = make_float4(ev.x * sv.x, ev.y * sv.y, ev.z * sv.z, ev.w * sv.w);
        float4 h, l;
        split2(sv.x, h.x, l.x); split2(sv.y, h.y, l.y);
        split2(sv.z, h.z, l.z); split2(sv.w, h.w, l.w);
        sm4[OFF4_SH + lr * APAD4 + lc] = h;
        sm4[OFF4_SL + lr * APAD4 + lc] = l;
        split2(es.x, h.x, l.x); split2(es.y, h.y, l.y);
        split2(es.z, h.z, l.z); split2(es.w, h.w, l.w);
        sm4[OFF4_ESH + lr * APAD4 + lc] = h;
        sm4[OFF4_ESL + lr * APAD4 + lc] = l;
    }
    __syncthreads();

    const float* sSH  = sm + OFF4_SH  * 4;
    const float* sSL  = sm + OFF4_SL  * 4;
    const float* sEH  = sm + OFF4_ESH * 4;
    const float* sEL  = sm + OFF4_ESL * 4;
    const float* sWGH = sm + OFF4_WGH * 4;
    const float* sWGL = sm + OFF4_WGL * 4;
    const float* sWBH = sm + OFF4_WBH * 4;
    const float* sWBL = sm + OFF4_WBL * 4;

    int warp = tid >> 5;
    int lane = tid & 31;
    int g  = lane >> 2;      // 0..7  (fragment row group)
    int c  = lane & 3;       // 0..3  (fragment col group)
    int r0 = warp * 16;      // block-local row base for this warp

    float cg[8][4], cb[8][4];
#pragma unroll
    for (int nt = 0; nt < 8; nt++)
#pragma unroll
        for (int i = 0; i < 4; i++) { cg[nt][i] = 0.f; cb[nt][i] = 0.f; }

#pragma unroll
    for (int k = 0; k < 8; k++) {
        int k8 = k * 8;
        int ab = (r0 + g) * APAD + k8 + c;
        uint32_t sh[4], sl[4], eh[4], el[4];
        sh[0] = __float_as_uint(sSH[ab]);                sh[1] = __float_as_uint(sSH[ab + 8 * APAD]);
        sh[2] = __float_as_uint(sSH[ab + 4]);            sh[3] = __float_as_uint(sSH[ab + 8 * APAD + 4]);
        sl[0] = __float_as_uint(sSL[ab]);                sl[1] = __float_as_uint(sSL[ab + 8 * APAD]);
        sl[2] = __float_as_uint(sSL[ab + 4]);            sl[3] = __float_as_uint(sSL[ab + 8 * APAD + 4]);
        eh[0] = __float_as_uint(sEH[ab]);                eh[1] = __float_as_uint(sEH[ab + 8 * APAD]);
        eh[2] = __float_as_uint(sEH[ab + 4]);            eh[3] = __float_as_uint(sEH[ab + 8 * APAD + 4]);
        el[0] = __float_as_uint(sEL[ab]);                el[1] = __float_as_uint(sEL[ab + 8 * APAD]);
        el[2] = __float_as_uint(sEL[ab + 4]);            el[3] = __float_as_uint(sEL[ab + 8 * APAD + 4]);

#pragma unroll
        for (int nt = 0; nt < 8; nt++) {
            int bb_ = (k8 + c) * WPAD + nt * 8 + g;
            uint32_t wh0 = __float_as_uint(sWGH[bb_]);
            uint32_t wh1 = __float_as_uint(sWGH[bb_ + 4 * WPAD]);
            uint32_t wl0 = __float_as_uint(sWGL[bb_]);
            uint32_t wl1 = __float_as_uint(sWGL[bb_ + 4 * WPAD]);
            mma_tf32(cg[nt], sl[0], sl[1], sl[2], sl[3], wh0, wh1);
            mma_tf32(cg[nt], sh[0], sh[1], sh[2], sh[3], wl0, wl1);
            mma_tf32(cg[nt], sh[0], sh[1], sh[2], sh[3], wh0, wh1);

            uint32_t vh0 = __float_as_uint(sWBH[bb_]);
            uint32_t vh1 = __float_as_uint(sWBH[bb_ + 4 * WPAD]);
            uint32_t vl0 = __float_as_uint(sWBL[bb_]);
            uint32_t vl1 = __float_as_uint(sWBL[bb_ + 4 * WPAD]);
            mma_tf32(cb[nt], el[0], el[1], el[2], el[3], vh0, vh1);
            mma_tf32(cb[nt], eh[0], eh[1], eh[2], eh[3], vl0, vl1);
            mma_tf32(cb[nt], eh[0], eh[1], eh[2], eh[3], vh0, vh1);
        }
    }

    // ---- epilogue: bias + leaky + combine + l2norm + stores ----
    float2 neA[8], neB[8];     // rows (r0+g) and (r0+g+8)
    float sA = 0.f, sB = 0.f;
#pragma unroll
    for (int nt = 0; nt < 8; nt++) {
        int col0 = nt * 8 + 2 * c;
        float2 bgv = __ldg(reinterpret_cast<const float2*>(bg + col0));
        float2 bbv = __ldg(reinterpret_cast<const float2*>(bb + col0));
        float g0 = cg[nt][0] + bgv.x;  g0 = (g0 > 0.f) ? g0 : 0.2f * g0;
        float g1 = cg[nt][1] + bgv.y;  g1 = (g1 > 0.f) ? g1 : 0.2f * g1;
        float g2 = cg[nt][2] + bgv.x;  g2 = (g2 > 0.f) ? g2 : 0.2f * g2;
        float g3 = cg[nt][3] + bgv.y;  g3 = (g3 > 0.f) ? g3 : 0.2f * g3;
        float h0 = cb[nt][0] + bbv.x;  h0 = (h0 > 0.f) ? h0 : 0.2f * h0;
        float h1 = cb[nt][1] + bbv.y;  h1 = (h1 > 0.f) ? h1 : 0.2f * h1;
        float h2 = cb[nt][2] + bbv.x;  h2 = (h2 > 0.f) ? h2 : 0.2f * h2;
        float h3 = cb[nt][3] + bbv.y;  h3 = (h3 > 0.f) ? h3 : 0.2f * h3;
        float a0 = g0 + h0, a1 = g1 + h1;
        float b0 = g2 + h2, b1 = g3 + h3;
        neA[nt] = make_float2(a0, a1);
        neB[nt] = make_float2(b0, b1);
        sA = fmaf(a0, a0, fmaf(a1, a1, sA));
        sB = fmaf(b0, b0, fmaf(b1, b1, sB));
    }
    sA += __shfl_xor_sync(0xffffffffu, sA, 1);
    sA += __shfl_xor_sync(0xffffffffu, sA, 2);
    sB += __shfl_xor_sync(0xffffffffu, sB, 1);
    sB += __shfl_xor_sync(0xffffffffu, sB, 2);
    float invA = 1.f / fmaxf(sqrtf(sA), 1e-12f);
    float invB = 1.f / fmaxf(sqrtf(sB), 1e-12f);

    int growA = rowbase + r0 + g;
    int growB = growA + 8;
#pragma unroll
    for (int nt = 0; nt < 8; nt++) {
        int col0 = nt * 8 + 2 * c;
        if (growA < NN) {
            *reinterpret_cast<float2*>(&g_ego[growA * 64 + col0]) = neA[nt];
            *reinterpret_cast<float2*>(&out[growA * 256 + koff + col0]) =
                make_float2(neA[nt].x * invA, neA[nt].y * invA);
        }
        if (growB < NN) {
            *reinterpret_cast<float2*>(&g_ego[growB * 64 + col0]) = neB[nt];
            *reinterpret_cast<float2*>(&out[growB * 256 + koff + col0]) =
                make_float2(neB[nt].x * invB, neB[nt].y * invB);
        }
    }
}

// ---------------------------------------------------------------------------
extern "C" void kernel_launch(void* const* d_in, const int* in_sizes, int n_in,
                              void* d_out, int out_size) {
    const float* ue = (const float*)d_in[0];
    const float* ie = (const float*)d_in[1];
    const float* Wg[3] = {(const float*)d_in[2],  (const float*)d_in[6],  (const float*)d_in[10]};
    const float* bg[3] = {(const float*)d_in[3],  (const float*)d_in[7],  (const float*)d_in[11]};
    const float* Wb[3] = {(const float*)d_in[4],  (const float*)d_in[8],  (const float*)d_in[12]};
    const float* bb[3] = {(const float*)d_in[5],  (const float*)d_in[9],  (const float*)d_in[13]};
    const float* vals = (const float*)d_in[14];
    const int*   rows = (const int*)d_in[15];
    const int*   cols = (const int*)d_in[16];
    float* out = (float*)d_out;

    cudaFuncSetAttribute(layer_kernel,
                         cudaFuncAttributeMaxDynamicSharedMemorySize, SMEM_BYTES);

    prof_shim_kernel<<<1, 1>>>();   // shifts ncu -s 5 onto a layer_kernel launch
    init_kernel<<<(NN * 16 + 255) / 256, 256>>>(ue, ie, out);
    for (int k = 0; k < 3; k++) {
        spmm_kernel<<<(EE * 4 + 255) / 256, 256>>>(vals, rows, cols);
        layer_kernel<<<(NN + 127) / 128, 256, SMEM_BYTES>>>(
            Wg[k], bg[k], Wb[k], bb[k], out, (k + 1) * 64);
    }
}

// round 9
// speedup vs baseline: 1.0961x; 1.0085x over previous
#include <cuda_runtime.h>
#include <cstdint>

#define NUSER 50000
#define NITEM 100000
#define NN    150000
#define DD    64
#define EE    2400000

// scratch: static device globals (no runtime allocation allowed)
__device__ float g_ego[NN * DD];   // 38.4 MB
__device__ float g_side[NN * DD];  // 38.4 MB

// tiny shim so ncu (-s 5 -c 1) lands on a layer_kernel launch
__global__ void prof_shim_kernel() {}

// ---------------------------------------------------------------------------
// init: ego = concat(user_emb, item_emb); side = 0; out[:, 0:64] = ego (raw)
// ---------------------------------------------------------------------------
__global__ void init_kernel(const float* __restrict__ ue,
                            const float* __restrict__ ie,
                            float* __restrict__ out) {
    int i4 = blockIdx.x * blockDim.x + threadIdx.x;  // float4 index
    if (i4 >= NN * 16) return;
    int row = i4 >> 4;
    int q   = i4 & 15;
    float4 v;
    if (row < NUSER) v = reinterpret_cast<const float4*>(ue)[i4];
    else             v = reinterpret_cast<const float4*>(ie)[i4 - NUSER * 16];
    reinterpret_cast<float4*>(g_ego)[i4]  = v;
    reinterpret_cast<float4*>(g_side)[i4] = make_float4(0.f, 0.f, 0.f, 0.f);
    reinterpret_cast<float4*>(out)[row * 64 + q] = v;
}

// ---------------------------------------------------------------------------
// SpMM: side[r] += vals[e] * ego[c].  4 threads/edge, each owns 4 float4s.
// ---------------------------------------------------------------------------
__global__ void spmm_kernel(const float* __restrict__ vals,
                            const int*   __restrict__ rows,
                            const int*   __restrict__ cols) {
    int t = blockIdx.x * blockDim.x + threadIdx.x;  // EE*4 = 9.6M
    if (t >= EE * 4) return;
    int e = t >> 2;
    int q = t & 3;
    int c   = __ldg(cols + e);
    int r   = __ldg(rows + e);
    float v = __ldg(vals + e);
    const float4* src = reinterpret_cast<const float4*>(g_ego + (size_t)c * DD) + q;
    float4*       dst = reinterpret_cast<float4*>(g_side + (size_t)r * DD) + q;

    float4 x[4];
#pragma unroll
    for (int j = 0; j < 4; j++) x[j] = __ldg(src + j * 4);
#pragma unroll
    for (int j = 0; j < 4; j++) {
        x[j].x *= v; x[j].y *= v; x[j].z *= v; x[j].w *= v;
#if __CUDA_ARCH__ >= 900
        atomicAdd(dst + j * 4, x[j]);
#else
        float* p = reinterpret_cast<float*>(dst + j * 4);
        atomicAdd(p + 0, x[j].x); atomicAdd(p + 1, x[j].y);
        atomicAdd(p + 2, x[j].z); atomicAdd(p + 3, x[j].w);
#endif
    }
}

// ---------------------------------------------------------------------------
// tf32 helpers
// ---------------------------------------------------------------------------
__device__ __forceinline__ uint32_t f2tf32(float f) {
    uint32_t u;
    asm("cvt.rna.tf32.f32 %0, %1;" : "=r"(u) : "f"(f));
    return u;
}
__device__ __forceinline__ void split2(float f, float& hi, float& lo) {
    uint32_t h = f2tf32(f);
    hi = __uint_as_float(h);
    lo = __uint_as_float(f2tf32(f - hi));
}
__device__ __forceinline__ void splitu(float f, uint32_t& hi, uint32_t& lo) {
    hi = f2tf32(f);
    lo = f2tf32(f - __uint_as_float(hi));
}
__device__ __forceinline__ void mma_tf32(float c[4],
                                         uint32_t a0, uint32_t a1, uint32_t a2, uint32_t a3,
                                         uint32_t b0, uint32_t b1) {
    asm volatile(
        "mma.sync.aligned.m16n8k8.row.col.f32.tf32.tf32.f32 "
        "{%0,%1,%2,%3}, {%4,%5,%6,%7}, {%8,%9}, {%0,%1,%2,%3};"
        : "+f"(c[0]), "+f"(c[1]), "+f"(c[2]), "+f"(c[3])
        : "r"(a0), "r"(a1), "r"(a2), "r"(a3), "r"(b0), "r"(b1));
}

// swizzles (float-index): conflict-free for mma fragment loads, float4-aligned
#define SW_A(r, c)  ((r) * 64 + ((c) ^ (((r) & 7) << 2)))
#define SW_W(k, n)  ((k) * 64 + ((n) ^ (((k) & 3) << 3)))

// float4 offsets in dynamic smem
#define OFF4_WGH 0          // 64*16 = 1024 float4 each
#define OFF4_WGL 1024
#define OFF4_WBH 2048
#define OFF4_WBL 3072
#define OFF4_S   4096       // 128*16 = 2048 float4 each
#define OFF4_ES  6144
#define OFF4_SQ  8192       // 2*128 floats = 64 float4
#define SMEM_BYTES ((8256) * 16)   // 132096 B

// ---------------------------------------------------------------------------
// Fused dense layer (3xTF32 mma.sync m16n8k8):
//   Block = 512 thr / 16 warps, tile 128 rows x 64 cols.
//   Warp (wx,wy): rows [wx*16,+16) x cols [wy*32,+32); nt=4 n-tiles.
// W hi/lo presplit in smem (swizzled, conflict-free); S/ES raw in smem,
// split to tf32 hi/lo in registers per k-step (8 splits/k, cheap).
// 129KB smem -> 16 warps/SM (2x R8).
// ---------------------------------------------------------------------------
__global__ __launch_bounds__(512) void layer_kernel(
    const float* __restrict__ Wg, const float* __restrict__ bg,
    const float* __restrict__ Wb, const float* __restrict__ bb,
    float* __restrict__ out, int koff) {
    extern __shared__ float sm[];
    float4* sm4 = reinterpret_cast<float4*>(sm);

    int tid = threadIdx.x;
    int rowbase = blockIdx.x * 128;

    // ---- stage weights, pre-split hi/lo, swizzled ----
#pragma unroll
    for (int i = 0; i < 2; i++) {
        int id = tid + i * 512;           // float4 id, 0..1023
        int k  = id >> 4, lc = id & 15;
        int sidx = k * 16 + (lc ^ ((k & 3) << 1));   // SW_W in float4 units
        float4 wg4 = reinterpret_cast<const float4*>(Wg)[id];
        float4 wb4 = reinterpret_cast<const float4*>(Wb)[id];
        float4 h, l;
        split2(wg4.x, h.x, l.x); split2(wg4.y, h.y, l.y);
        split2(wg4.z, h.z, l.z); split2(wg4.w, h.w, l.w);
        sm4[OFF4_WGH + sidx] = h;
        sm4[OFF4_WGL + sidx] = l;
        split2(wb4.x, h.x, l.x); split2(wb4.y, h.y, l.y);
        split2(wb4.z, h.z, l.z); split2(wb4.w, h.w, l.w);
        sm4[OFF4_WBH + sidx] = h;
        sm4[OFF4_WBL + sidx] = l;
    }
    // ---- stage S / ES raw, swizzled; clear side ----
#pragma unroll
    for (int i = 0; i < 4; i++) {
        int id = tid + i * 512;           // float4 id, 0..2047
        int lr = id >> 4, lc = id & 15;
        int grow = rowbase + lr;
        float4 sv = make_float4(0.f, 0.f, 0.f, 0.f);
        float4 ev = sv;
        if (grow < NN) {
            int gi4 = grow * 16 + lc;
            sv = reinterpret_cast<float4*>(g_side)[gi4];
            ev = reinterpret_cast<float4*>(g_ego)[gi4];
            reinterpret_cast<float4*>(g_side)[gi4] = make_float4(0.f, 0.f, 0.f, 0.f);
        }
        int aidx = lr * 16 + (lc ^ (lr & 7));        // SW_A in float4 units
        sm4[OFF4_S  + aidx] = sv;
        sm4[OFF4_ES + aidx] =
            make_float4(ev.x * sv.x, ev.y * sv.y, ev.z * sv.z, ev.w * sv.w);
    }
    __syncthreads();

    const float* sS   = sm + OFF4_S   * 4;
    const float* sES  = sm + OFF4_ES  * 4;
    const float* sWGH = sm + OFF4_WGH * 4;
    const float* sWGL = sm + OFF4_WGL * 4;
    const float* sWBH = sm + OFF4_WBH * 4;
    const float* sWBL = sm + OFF4_WBL * 4;
    float*       sSQ  = sm + OFF4_SQ  * 4;

    int warp = tid >> 5;
    int lane = tid & 31;
    int wy = warp & 1;        // col half
    int wx = warp >> 1;       // row group 0..7
    int g  = lane >> 2;       // 0..7
    int c  = lane & 3;        // 0..3
    int r0 = wx * 16;
    int nb = wy * 32;         // n-tile base

    float cg[4][4], cb[4][4];
#pragma unroll
    for (int nt = 0; nt < 4; nt++)
#pragma unroll
        for (int i = 0; i < 4; i++) { cg[nt][i] = 0.f; cb[nt][i] = 0.f; }

#pragma unroll
    for (int k = 0; k < 8; k++) {
        int k8 = k * 8;
        int rA = r0 + g, rB = r0 + g + 8;
        int c0_ = k8 + c, c1_ = k8 + c + 4;
        uint32_t sh[4], sl[4], eh[4], el[4];
        splitu(sS [SW_A(rA, c0_)], sh[0], sl[0]);
        splitu(sS [SW_A(rB, c0_)], sh[1], sl[1]);
        splitu(sS [SW_A(rA, c1_)], sh[2], sl[2]);
        splitu(sS [SW_A(rB, c1_)], sh[3], sl[3]);
        splitu(sES[SW_A(rA, c0_)], eh[0], el[0]);
        splitu(sES[SW_A(rB, c0_)], eh[1], el[1]);
        splitu(sES[SW_A(rA, c1_)], eh[2], el[2]);
        splitu(sES[SW_A(rB, c1_)], eh[3], el[3]);

#pragma unroll
        for (int nt = 0; nt < 4; nt++) {
            int ncol = nb + nt * 8 + g;
            int b0i = SW_W(k8 + c, ncol);
            int b1i = SW_W(k8 + c + 4, ncol);
            uint32_t wh0 = __float_as_uint(sWGH[b0i]);
            uint32_t wh1 = __float_as_uint(sWGH[b1i]);
            uint32_t wl0 = __float_as_uint(sWGL[b0i]);
            uint32_t wl1 = __float_as_uint(sWGL[b1i]);
            mma_tf32(cg[nt], sl[0], sl[1], sl[2], sl[3], wh0, wh1);
            mma_tf32(cg[nt], sh[0], sh[1], sh[2], sh[3], wl0, wl1);
            mma_tf32(cg[nt], sh[0], sh[1], sh[2], sh[3], wh0, wh1);

            uint32_t vh0 = __float_as_uint(sWBH[b0i]);
            uint32_t vh1 = __float_as_uint(sWBH[b1i]);
            uint32_t vl0 = __float_as_uint(sWBL[b0i]);
            uint32_t vl1 = __float_as_uint(sWBL[b1i]);
            mma_tf32(cb[nt], el[0], el[1], el[2], el[3], vh0, vh1);
            mma_tf32(cb[nt], eh[0], eh[1], eh[2], eh[3], vl0, vl1);
            mma_tf32(cb[nt], eh[0], eh[1], eh[2], eh[3], vh0, vh1);
        }
    }

    // ---- epilogue: bias + leaky + combine; partial l2 sums ----
    float2 neA[4], neB[4];       // rows (r0+g) and (r0+g+8)
    float sA = 0.f, sB = 0.f;
#pragma unroll
    for (int nt = 0; nt < 4; nt++) {
        int col0 = nb + nt * 8 + 2 * c;
        float2 bgv = __ldg(reinterpret_cast<const float2*>(bg + col0));
        float2 bbv = __ldg(reinterpret_cast<const float2*>(bb + col0));
        float g0 = cg[nt][0] + bgv.x;  g0 = (g0 > 0.f) ? g0 : 0.2f * g0;
        float g1 = cg[nt][1] + bgv.y;  g1 = (g1 > 0.f) ? g1 : 0.2f * g1;
        float g2 = cg[nt][2] + bgv.x;  g2 = (g2 > 0.f) ? g2 : 0.2f * g2;
        float g3 = cg[nt][3] + bgv.y;  g3 = (g3 > 0.f) ? g3 : 0.2f * g3;
        float h0 = cb[nt][0] + bbv.x;  h0 = (h0 > 0.f) ? h0 : 0.2f * h0;
        float h1 = cb[nt][1] + bbv.y;  h1 = (h1 > 0.f) ? h1 : 0.2f * h1;
        float h2 = cb[nt][2] + bbv.x;  h2 = (h2 > 0.f) ? h2 : 0.2f * h2;
        float h3 = cb[nt][3] + bbv.y;  h3 = (h3 > 0.f) ? h3 : 0.2f * h3;
        float a0 = g0 + h0, a1 = g1 + h1;
        float b0 = g2 + h2, b1 = g3 + h3;
        neA[nt] = make_float2(a0, a1);
        neB[nt] = make_float2(b0, b1);
        sA = fmaf(a0, a0, fmaf(a1, a1, sA));
        sB = fmaf(b0, b0, fmaf(b1, b1, sB));
    }
    // reduce over the 4 c-lanes (32-col partial for this warp)
    sA += __shfl_xor_sync(0xffffffffu, sA, 1);
    sA += __shfl_xor_sync(0xffffffffu, sA, 2);
    sB += __shfl_xor_sync(0xffffffffu, sB, 1);
    sB += __shfl_xor_sync(0xffffffffu, sB, 2);
    // combine the two column-halves through smem
    if (c == 0) {
        sSQ[wy * 128 + r0 + g]     = sA;
        sSQ[wy * 128 + r0 + g + 8] = sB;
    }
    __syncthreads();
    float totA = sSQ[r0 + g]     + sSQ[128 + r0 + g];
    float totB = sSQ[r0 + g + 8] + sSQ[128 + r0 + g + 8];
    float invA = 1.f / fmaxf(sqrtf(totA), 1e-12f);
    float invB = 1.f / fmaxf(sqrtf(totB), 1e-12f);

    int growA = rowbase + r0 + g;
    int growB = growA + 8;
#pragma unroll
    for (int nt = 0; nt < 4; nt++) {
        int col0 = nb + nt * 8 + 2 * c;
        if (growA < NN) {
            *reinterpret_cast<float2*>(&g_ego[growA * 64 + col0]) = neA[nt];
            *reinterpret_cast<float2*>(&out[growA * 256 + koff + col0]) =
                make_float2(neA[nt].x * invA, neA[nt].y * invA);
        }
        if (growB < NN) {
            *reinterpret_cast<float2*>(&g_ego[growB * 64 + col0]) = neB[nt];
            *reinterpret_cast<float2*>(&out[growB * 256 + koff + col0]) =
                make_float2(neB[nt].x * invB, neB[nt].y * invB);
        }
    }
}

// ---------------------------------------------------------------------------
extern "C" void kernel_launch(void* const* d_in, const int* in_sizes, int n_in,
                              void* d_out, int out_size) {
    const float* ue = (const float*)d_in[0];
    const float* ie = (const float*)d_in[1];
    const float* Wg[3] = {(const float*)d_in[2],  (const float*)d_in[6],  (const float*)d_in[10]};
    const float* bg[3] = {(const float*)d_in[3],  (const float*)d_in[7],  (const float*)d_in[11]};
    const float* Wb[3] = {(const float*)d_in[4],  (const float*)d_in[8],  (const float*)d_in[12]};
    const float* bb[3] = {(const float*)d_in[5],  (const float*)d_in[9],  (const float*)d_in[13]};
    const float* vals = (const float*)d_in[14];
    const int*   rows = (const int*)d_in[15];
    const int*   cols = (const int*)d_in[16];
    float* out = (float*)d_out;

    cudaFuncSetAttribute(layer_kernel,
                         cudaFuncAttributeMaxDynamicSharedMemorySize, SMEM_BYTES);

    prof_shim_kernel<<<1, 1>>>();   // shifts ncu -s 5 onto a layer_kernel launch
    init_kernel<<<(NN * 16 + 255) / 256, 256>>>(ue, ie, out);
    for (int k = 0; k < 3; k++) {
        spmm_kernel<<<(EE * 4 + 255) / 256, 256>>>(vals, rows, cols);
        layer_kernel<<<(NN + 127) / 128, 512, SMEM_BYTES>>>(
            Wg[k], bg[k], Wb[k], bb[k], out, (k + 1) * 64);
    }
}